// round 2
// baseline (speedup 1.0000x reference)
#include <cuda_runtime.h>
#include <cuda_bf16.h>
#include <cstdint>
#include <math.h>

#define N_ROWS 8192
#define DIMK   1024

// ---------------- scratch (static device memory, no allocs) ----------------
__device__ __align__(16) float          g_Xn[N_ROWS * DIMK];   // 32 MB normalized fp32
__device__ __align__(16) __nv_bfloat16  g_Xb[N_ROWS * DIMK];   // 16 MB bf16 row-major
__device__ float g_bestv[2 * N_ROWS];
__device__ int   g_besti[2 * N_ROWS];
__device__ float g_logd[N_ROWS];

// ---------------- helpers ----------------
__device__ __forceinline__ uint32_t smem_u32(const void* p) {
    uint32_t a;
    asm("{ .reg .u64 t; cvta.to.shared.u64 t, %1; cvt.u32.u64 %0, t; }" : "=r"(a) : "l"(p));
    return a;
}
__device__ __forceinline__ void cp16(uint32_t dst, const void* src) {
    asm volatile("cp.async.cg.shared.global [%0], [%1], 16;" :: "r"(dst), "l"(src));
}
__device__ __forceinline__ void ldsm4(uint32_t& r0, uint32_t& r1, uint32_t& r2, uint32_t& r3,
                                      uint32_t addr) {
    asm volatile("ldmatrix.sync.aligned.m8n8.x4.shared.b16 {%0,%1,%2,%3}, [%4];"
                 : "=r"(r0), "=r"(r1), "=r"(r2), "=r"(r3) : "r"(addr));
}
__device__ __forceinline__ void mma16816(float* c, uint32_t a0, uint32_t a1, uint32_t a2,
                                         uint32_t a3, uint32_t b0, uint32_t b1) {
    asm volatile("mma.sync.aligned.m16n8k16.row.col.f32.bf16.bf16.f32 "
                 "{%0,%1,%2,%3}, {%4,%5,%6,%7}, {%8,%9}, {%0,%1,%2,%3};"
                 : "+f"(c[0]), "+f"(c[1]), "+f"(c[2]), "+f"(c[3])
                 : "r"(a0), "r"(a1), "r"(a2), "r"(a3), "r"(b0), "r"(b1));
}

// ---------------- kernel 1: normalize rows, write fp32 + bf16 copies ----------------
__global__ void koleo_normalize_kernel(const float* __restrict__ x) {
    const int row = blockIdx.x;
    const int tid = threadIdx.x;  // 256 threads, 4 elems each
    const float4 v = ((const float4*)(x + (size_t)row * DIMK))[tid];
    float ss = v.x * v.x + v.y * v.y + v.z * v.z + v.w * v.w;
    #pragma unroll
    for (int o = 16; o; o >>= 1) ss += __shfl_xor_sync(0xFFFFFFFFu, ss, o);
    __shared__ float ws[9];
    if ((tid & 31) == 0) ws[tid >> 5] = ss;
    __syncthreads();
    if (tid == 0) {
        float t = 0.f;
        #pragma unroll
        for (int i = 0; i < 8; i++) t += ws[i];
        ws[8] = 1.f / fmaxf(sqrtf(t), 1e-8f);
    }
    __syncthreads();
    const float s = ws[8];
    float4 y; y.x = v.x * s; y.y = v.y * s; y.z = v.z * s; y.w = v.w * s;
    ((float4*)(g_Xn + (size_t)row * DIMK))[tid] = y;

    __nv_bfloat162 h0 = __floats2bfloat162_rn(y.x, y.y);
    __nv_bfloat162 h1 = __floats2bfloat162_rn(y.z, y.w);
    uint2 u;
    u.x = *(const uint32_t*)&h0;
    u.y = *(const uint32_t*)&h1;
    *(uint2*)(g_Xb + (size_t)row * DIMK + tid * 4) = u;
}

// ---------------- kernel 2: bf16 mma.sync GEMM + fused per-row argmax ----------------
// grid (64, 2): 64 row-blocks of 128 rows; each CTA scans 4096 columns.
// 256 threads = 8 warps, warp grid 2 (m) x 4 (n): warp computes 64x32 of the 128x128 tile.
// Stage: K-chunk 64. A/B tiles 128x64 bf16, 16KB each, double-buffered (64KB smem).
// Swizzle: 16B chunk index within a row XORed with (row & 7).

__device__ __forceinline__ void copy_stage(uint32_t dst, const __nv_bfloat16* gA,
                                           const __nv_bfloat16* gB, int kbase, int tid) {
    #pragma unroll
    for (int i = 0; i < 4; i++) {
        const int idx = tid + i * 256;     // 0..1023
        const int r = idx >> 3, ch = idx & 7;
        const uint32_t doff = (uint32_t)r * 128u + ((uint32_t)(ch ^ (r & 7)) << 4);
        const size_t soff = (size_t)r * DIMK + kbase + ch * 8;
        cp16(dst + doff, gA + soff);
        cp16(dst + 16384u + doff, gB + soff);
    }
    asm volatile("cp.async.commit_group;" ::: "memory");
}

__global__ void __launch_bounds__(256, 1) koleo_argmax_kernel() {
    extern __shared__ unsigned char smem[];
    const uint32_t sbase = smem_u32(smem);
    const int tid = threadIdx.x;
    const int lane = tid & 31;
    const int wid = tid >> 5;
    const int wm = wid & 1;        // m-stripe: 0/1 -> rows [wm*64, wm*64+64)
    const int wn = wid >> 1;       // n-stripe: 0..3 -> cols [wn*32, wn*32+32)
    const int rb = blockIdx.x;
    const int half = blockIdx.y;

    float bestv[8];
    int   besti[8];
    #pragma unroll
    for (int i = 0; i < 8; i++) { bestv[i] = -2.f; besti[i] = 0; }

    const __nv_bfloat16* gA = g_Xb + (size_t)rb * 128 * DIMK;

    for (int nt = 0; nt < 32; nt++) {
        const int cb = half * 32 + nt;
        const __nv_bfloat16* gB = g_Xb + (size_t)cb * 128 * DIMK;

        float c[4][4][4];
        #pragma unroll
        for (int a = 0; a < 4; a++)
            #pragma unroll
            for (int b = 0; b < 4; b++)
                #pragma unroll
                for (int r = 0; r < 4; r++) c[a][b][r] = 0.f;

        copy_stage(sbase, gA, gB, 0, tid);

        for (int s = 0; s < 16; s++) {
            if (s + 1 < 16) {
                copy_stage(sbase + (uint32_t)((s + 1) & 1) * 32768u, gA, gB, (s + 1) * 64, tid);
                asm volatile("cp.async.wait_group 1;" ::: "memory");
            } else {
                asm volatile("cp.async.wait_group 0;" ::: "memory");
            }
            __syncthreads();

            const uint32_t A = sbase + (uint32_t)(s & 1) * 32768u;
            const uint32_t B = A + 16384u;

            #pragma unroll
            for (int t = 0; t < 4; t++) {            // k16 steps within the 64-chunk
                const uint32_t kc = (uint32_t)(t << 1) + (uint32_t)(lane >> 4);  // 16B-chunk idx
                // B fragments: two ldmatrix.x4 over n16 x k16 blocks
                uint32_t bf[2][4];
                #pragma unroll
                for (int nh = 0; nh < 2; nh++) {
                    const uint32_t r = (uint32_t)(wn * 32 + nh * 16 + (lane & 15));
                    const uint32_t addr = B + r * 128u + ((kc ^ (r & 7u)) << 4);
                    ldsm4(bf[nh][0], bf[nh][1], bf[nh][2], bf[nh][3], addr);
                }
                #pragma unroll
                for (int mt = 0; mt < 4; mt++) {
                    const uint32_t r = (uint32_t)(wm * 64 + mt * 16 + (lane & 15));
                    const uint32_t addr = A + r * 128u + ((kc ^ (r & 7u)) << 4);
                    uint32_t af[4];
                    ldsm4(af[0], af[1], af[2], af[3], addr);
                    #pragma unroll
                    for (int n2 = 0; n2 < 4; n2++) {
                        mma16816(c[mt][n2], af[0], af[1], af[2], af[3],
                                 bf[n2 >> 1][n2 & 1], bf[n2 >> 1][2 + (n2 & 1)]);
                    }
                }
            }
            __syncthreads();
        }

        // fold this 128x128 tile into the per-thread running argmax
        const int colbase = cb * 128 + wn * 32;
        const int rowbase = rb * 128 + wm * 64;
        #pragma unroll
        for (int mt = 0; mt < 4; mt++) {
            #pragma unroll
            for (int rh = 0; rh < 2; rh++) {
                const int rloc = mt * 2 + rh;
                const int grow = rowbase + mt * 16 + (lane >> 2) + rh * 8;
                #pragma unroll
                for (int n2 = 0; n2 < 4; n2++) {
                    #pragma unroll
                    for (int h = 0; h < 2; h++) {
                        const int col = colbase + n2 * 8 + (lane & 3) * 2 + h;
                        const float v = c[mt][n2][rh * 2 + h];
                        if (col != grow && v > bestv[rloc]) {
                            bestv[rloc] = v; besti[rloc] = col;
                        }
                    }
                }
            }
        }
    }

    // reduce (max, smallest idx on tie) across the 4 lanes sharing each row
    #pragma unroll
    for (int rl = 0; rl < 8; rl++) {
        float v = bestv[rl]; int i = besti[rl];
        #pragma unroll
        for (int o = 1; o <= 2; o <<= 1) {
            const float ov = __shfl_xor_sync(0xFFFFFFFFu, v, o);
            const int   oi = __shfl_xor_sync(0xFFFFFFFFu, i, o);
            if (ov > v || (ov == v && oi < i)) { v = ov; i = oi; }
        }
        bestv[rl] = v; besti[rl] = i;
    }

    __syncthreads();  // done with stage buffers; reuse smem for reduction
    float* svals = (float*)smem;            // [128][4]
    int*   sidx  = (int*)(smem + 2048);     // [128][4]
    if ((lane & 3) == 0) {
        #pragma unroll
        for (int rl = 0; rl < 8; rl++) {
            const int row = wm * 64 + (rl >> 1) * 16 + (lane >> 2) + (rl & 1) * 8;
            svals[row * 4 + wn] = bestv[rl];
            sidx [row * 4 + wn] = besti[rl];
        }
    }
    __syncthreads();
    if (tid < 128) {
        float v = svals[tid * 4]; int i = sidx[tid * 4];
        #pragma unroll
        for (int w = 1; w < 4; w++) {
            const float ov = svals[tid * 4 + w];
            const int   oi = sidx [tid * 4 + w];
            if (ov > v || (ov == v && oi < i)) { v = ov; i = oi; }
        }
        g_bestv[half * N_ROWS + rb * 128 + tid] = v;
        g_besti[half * N_ROWS + rb * 128 + tid] = i;
    }
}

// ---------------- kernel 3: exact fp32 distance to argmax neighbor ----------------
__global__ void koleo_dist_kernel() {
    const int i = blockIdx.x;
    const int tid = threadIdx.x;  // 128
    const float v0 = g_bestv[i], v1 = g_bestv[N_ROWS + i];
    const int j = (v1 > v0) ? g_besti[N_ROWS + i] : g_besti[i];
    const float4* a = (const float4*)(g_Xn + (size_t)i * DIMK);
    const float4* b = (const float4*)(g_Xn + (size_t)j * DIMK);
    float s = 0.f;
    #pragma unroll
    for (int t = 0; t < 2; t++) {
        const int idx = tid + t * 128;
        const float4 av = a[idx], bv = b[idx];
        const float d0 = av.x - bv.x + 1e-8f;
        const float d1 = av.y - bv.y + 1e-8f;
        const float d2 = av.z - bv.z + 1e-8f;
        const float d3 = av.w - bv.w + 1e-8f;
        s += d0 * d0 + d1 * d1 + d2 * d2 + d3 * d3;
    }
    #pragma unroll
    for (int o = 16; o; o >>= 1) s += __shfl_xor_sync(0xFFFFFFFFu, s, o);
    __shared__ float ws[4];
    if ((tid & 31) == 0) ws[tid >> 5] = s;
    __syncthreads();
    if (tid == 0) {
        const float t = ws[0] + ws[1] + ws[2] + ws[3];
        g_logd[i] = logf(sqrtf(t) + 1e-8f);
    }
}

// ---------------- kernel 4: deterministic mean reduction ----------------
__global__ void koleo_finish_kernel(float* __restrict__ out) {
    const int tid = threadIdx.x;  // 1024
    float s = 0.f;
    #pragma unroll
    for (int t = 0; t < 8; t++) s += g_logd[tid + t * 1024];
    #pragma unroll
    for (int o = 16; o; o >>= 1) s += __shfl_xor_sync(0xFFFFFFFFu, s, o);
    __shared__ float ws[32];
    if ((tid & 31) == 0) ws[tid >> 5] = s;
    __syncthreads();
    if (tid == 0) {
        float t = 0.f;
        #pragma unroll
        for (int i = 0; i < 32; i++) t += ws[i];
        out[0] = -(t / 8192.f);
    }
}

// ---------------- launch ----------------
extern "C" void kernel_launch(void* const* d_in, const int* in_sizes, int n_in,
                              void* d_out, int out_size) {
    (void)in_sizes; (void)n_in; (void)out_size;
    const float* x = (const float*)d_in[0];
    cudaFuncSetAttribute(koleo_argmax_kernel, cudaFuncAttributeMaxDynamicSharedMemorySize, 65536);
    koleo_normalize_kernel<<<N_ROWS, 256>>>(x);
    koleo_argmax_kernel<<<dim3(64, 2, 1), 256, 65536>>>();
    koleo_dist_kernel<<<N_ROWS, 128>>>();
    koleo_finish_kernel<<<1, 1024>>>((float*)d_out);
}

// round 3
// speedup vs baseline: 1.0272x; 1.0272x over previous
#include <cuda_runtime.h>
#include <cuda_bf16.h>
#include <cstdint>
#include <math.h>

#define N_ROWS 8192
#define DIMK   1024

// ---------------- scratch (static device memory, no allocs) ----------------
__device__ __align__(16) float          g_Xn[N_ROWS * DIMK];   // 32 MB normalized fp32
__device__ __align__(16) __nv_bfloat16  g_Xb[N_ROWS * DIMK];   // 16 MB bf16 row-major
__device__ float g_bestv[2 * N_ROWS];
__device__ int   g_besti[2 * N_ROWS];
__device__ float g_logd[N_ROWS];

// ---------------- helpers ----------------
__device__ __forceinline__ uint32_t smem_u32(const void* p) {
    uint32_t a;
    asm("{ .reg .u64 t; cvta.to.shared.u64 t, %1; cvt.u32.u64 %0, t; }" : "=r"(a) : "l"(p));
    return a;
}
__device__ __forceinline__ void cp16(uint32_t dst, const void* src) {
    asm volatile("cp.async.cg.shared.global [%0], [%1], 16;" :: "r"(dst), "l"(src));
}
__device__ __forceinline__ void ldsm4(uint32_t& r0, uint32_t& r1, uint32_t& r2, uint32_t& r3,
                                      uint32_t addr) {
    asm volatile("ldmatrix.sync.aligned.m8n8.x4.shared.b16 {%0,%1,%2,%3}, [%4];"
                 : "=r"(r0), "=r"(r1), "=r"(r2), "=r"(r3) : "r"(addr));
}
__device__ __forceinline__ void mma16816(float* c, uint32_t a0, uint32_t a1, uint32_t a2,
                                         uint32_t a3, uint32_t b0, uint32_t b1) {
    asm volatile("mma.sync.aligned.m16n8k16.row.col.f32.bf16.bf16.f32 "
                 "{%0,%1,%2,%3}, {%4,%5,%6,%7}, {%8,%9}, {%0,%1,%2,%3};"
                 : "+f"(c[0]), "+f"(c[1]), "+f"(c[2]), "+f"(c[3])
                 : "r"(a0), "r"(a1), "r"(a2), "r"(a3), "r"(b0), "r"(b1));
}

// ---------------- kernel 1: normalize rows, write fp32 + bf16 copies ----------------
__global__ void koleo_normalize_kernel(const float* __restrict__ x) {
    const int row = blockIdx.x;
    const int tid = threadIdx.x;  // 256 threads, 4 elems each
    const float4 v = ((const float4*)(x + (size_t)row * DIMK))[tid];
    float ss = v.x * v.x + v.y * v.y + v.z * v.z + v.w * v.w;
    #pragma unroll
    for (int o = 16; o; o >>= 1) ss += __shfl_xor_sync(0xFFFFFFFFu, ss, o);
    __shared__ float ws[9];
    if ((tid & 31) == 0) ws[tid >> 5] = ss;
    __syncthreads();
    if (tid == 0) {
        float t = 0.f;
        #pragma unroll
        for (int i = 0; i < 8; i++) t += ws[i];
        ws[8] = 1.f / fmaxf(sqrtf(t), 1e-8f);
    }
    __syncthreads();
    const float s = ws[8];
    float4 y; y.x = v.x * s; y.y = v.y * s; y.z = v.z * s; y.w = v.w * s;
    ((float4*)(g_Xn + (size_t)row * DIMK))[tid] = y;

    __nv_bfloat162 h0 = __floats2bfloat162_rn(y.x, y.y);
    __nv_bfloat162 h1 = __floats2bfloat162_rn(y.z, y.w);
    uint2 u;
    u.x = *(const uint32_t*)&h0;
    u.y = *(const uint32_t*)&h1;
    *(uint2*)(g_Xb + (size_t)row * DIMK + tid * 4) = u;
}

// ---------------- kernel 2: bf16 mma.sync GEMM + fused per-row argmax ----------------
// grid (64, 2): 64 row-blocks of 128 rows; each CTA scans 2048... no: 4096 cols as
// 16 N-tiles of 256 columns. 8 warps in 2(m) x 4(n); warp tile 64x64.
// Stage = K-chunk 64: A 128x64 (16KB) + B 256x64 (32KB) = 48KB/buffer, 3 buffers.
// 256 global stages (16 tiles x 16 K-chunks), one __syncthreads per stage.
// Smem swizzle: 16B-chunk index XOR (row & 7).

#define STAGE_BYTES 49152u
#define NSTG 256

__device__ __forceinline__ void copy_stage(uint32_t sbase, int g, int rb, int half, int tid) {
    const int nt = g >> 4;
    const int s = g & 15;
    const uint32_t dst = sbase + (uint32_t)(((uint32_t)g) % 3u) * STAGE_BYTES;
    const __nv_bfloat16* gA = g_Xb + (size_t)(rb * 128) * DIMK + s * 64;
    const __nv_bfloat16* gB = g_Xb + (size_t)((half * 16 + nt) * 256) * DIMK + s * 64;
    // A: 128 rows x 8 chunks = 1024 chunks
    #pragma unroll
    for (int i = 0; i < 4; i++) {
        const int idx = tid + i * 256;
        const int r = idx >> 3, ch = idx & 7;
        const uint32_t doff = (uint32_t)r * 128u + ((uint32_t)(ch ^ (r & 7)) << 4);
        cp16(dst + doff, gA + (size_t)r * DIMK + ch * 8);
    }
    // B: 256 rows x 8 chunks = 2048 chunks
    #pragma unroll
    for (int i = 0; i < 8; i++) {
        const int idx = tid + i * 256;
        const int r = idx >> 3, ch = idx & 7;
        const uint32_t doff = (uint32_t)r * 128u + ((uint32_t)(ch ^ (r & 7)) << 4);
        cp16(dst + 16384u + doff, gB + (size_t)r * DIMK + ch * 8);
    }
    asm volatile("cp.async.commit_group;" ::: "memory");
}

__global__ void __launch_bounds__(256) koleo_argmax_kernel() {
    extern __shared__ unsigned char smem[];
    const uint32_t sbase = smem_u32(smem);
    const int tid = threadIdx.x;
    const int lane = tid & 31;
    const int wid = tid >> 5;
    const int wm = wid & 1;        // rows [wm*64, wm*64+64)
    const int wn = wid >> 1;       // cols [wn*64, wn*64+64) within the 256-wide tile
    const int rb = blockIdx.x;
    const int half = blockIdx.y;

    float bestv[8];
    int   besti[8];
    #pragma unroll
    for (int i = 0; i < 8; i++) { bestv[i] = -2.f; besti[i] = 0; }

    float c[4][8][4];
    #pragma unroll
    for (int a = 0; a < 4; a++)
        #pragma unroll
        for (int b = 0; b < 8; b++)
            #pragma unroll
            for (int r = 0; r < 4; r++) c[a][b][r] = 0.f;

    copy_stage(sbase, 0, rb, half, tid);
    copy_stage(sbase, 1, rb, half, tid);

    for (int g = 0; g < NSTG; g++) {
        if (g == NSTG - 1) {
            asm volatile("cp.async.wait_group 0;" ::: "memory");
        } else {
            asm volatile("cp.async.wait_group 1;" ::: "memory");
        }
        __syncthreads();
        if (g + 2 < NSTG) copy_stage(sbase, g + 2, rb, half, tid);

        const uint32_t A = sbase + (uint32_t)(((uint32_t)g) % 3u) * STAGE_BYTES;
        const uint32_t B = A + 16384u;

        #pragma unroll
        for (int t = 0; t < 4; t++) {
            const uint32_t kc = (uint32_t)(t << 1) + (uint32_t)(lane >> 4);
            uint32_t bf[4][4];
            #pragma unroll
            for (int nb = 0; nb < 4; nb++) {
                const uint32_t r = (uint32_t)(wn * 64 + nb * 16 + (lane & 15));
                const uint32_t addr = B + r * 128u + ((kc ^ (r & 7u)) << 4);
                ldsm4(bf[nb][0], bf[nb][1], bf[nb][2], bf[nb][3], addr);
            }
            #pragma unroll
            for (int mt = 0; mt < 4; mt++) {
                const uint32_t r = (uint32_t)(wm * 64 + mt * 16 + (lane & 15));
                const uint32_t addr = A + r * 128u + ((kc ^ (r & 7u)) << 4);
                uint32_t af[4];
                ldsm4(af[0], af[1], af[2], af[3], addr);
                #pragma unroll
                for (int j = 0; j < 8; j++) {
                    mma16816(c[mt][j], af[0], af[1], af[2], af[3],
                             bf[j >> 1][j & 1], bf[j >> 1][2 + (j & 1)]);
                }
            }
        }

        if ((g & 15) == 15) {
            // fold this 128x256 tile into the running per-row argmax, reset acc
            const int nt = g >> 4;
            const int colb = (half * 16 + nt) * 256 + wn * 64;
            const int rowb = rb * 128 + wm * 64;
            #pragma unroll
            for (int mt = 0; mt < 4; mt++) {
                #pragma unroll
                for (int rh = 0; rh < 2; rh++) {
                    const int rloc = mt * 2 + rh;
                    const int grow = rowb + mt * 16 + (lane >> 2) + rh * 8;
                    #pragma unroll
                    for (int j = 0; j < 8; j++) {
                        #pragma unroll
                        for (int h = 0; h < 2; h++) {
                            const int col = colb + j * 8 + (lane & 3) * 2 + h;
                            const float v = c[mt][j][rh * 2 + h];
                            if (col != grow && v > bestv[rloc]) {
                                bestv[rloc] = v; besti[rloc] = col;
                            }
                            c[mt][j][rh * 2 + h] = 0.f;
                        }
                    }
                }
            }
        }
    }

    // reduce (max, smallest idx on tie) across the 4 lanes sharing each row
    #pragma unroll
    for (int rl = 0; rl < 8; rl++) {
        float v = bestv[rl]; int i = besti[rl];
        #pragma unroll
        for (int o = 1; o <= 2; o <<= 1) {
            const float ov = __shfl_xor_sync(0xFFFFFFFFu, v, o);
            const int   oi = __shfl_xor_sync(0xFFFFFFFFu, i, o);
            if (ov > v || (ov == v && oi < i)) { v = ov; i = oi; }
        }
        bestv[rl] = v; besti[rl] = i;
    }

    __syncthreads();  // all warps done with stage buffers; reuse smem
    float* svals = (float*)smem;            // [128][4]
    int*   sidx  = (int*)(smem + 2048);     // [128][4]
    if ((lane & 3) == 0) {
        #pragma unroll
        for (int rl = 0; rl < 8; rl++) {
            const int row = wm * 64 + (rl >> 1) * 16 + (lane >> 2) + (rl & 1) * 8;
            svals[row * 4 + wn] = bestv[rl];
            sidx [row * 4 + wn] = besti[rl];
        }
    }
    __syncthreads();
    if (tid < 128) {
        float v = svals[tid * 4]; int i = sidx[tid * 4];
        #pragma unroll
        for (int w = 1; w < 4; w++) {
            const float ov = svals[tid * 4 + w];
            const int   oi = sidx [tid * 4 + w];
            if (ov > v || (ov == v && oi < i)) { v = ov; i = oi; }
        }
        g_bestv[half * N_ROWS + rb * 128 + tid] = v;
        g_besti[half * N_ROWS + rb * 128 + tid] = i;
    }
}

// ---------------- kernel 3: exact fp32 distance to argmax neighbor ----------------
__global__ void koleo_dist_kernel() {
    const int i = blockIdx.x;
    const int tid = threadIdx.x;  // 128
    const float v0 = g_bestv[i], v1 = g_bestv[N_ROWS + i];
    const int j = (v1 > v0) ? g_besti[N_ROWS + i] : g_besti[i];
    const float4* a = (const float4*)(g_Xn + (size_t)i * DIMK);
    const float4* b = (const float4*)(g_Xn + (size_t)j * DIMK);
    float s = 0.f;
    #pragma unroll
    for (int t = 0; t < 2; t++) {
        const int idx = tid + t * 128;
        const float4 av = a[idx], bv = b[idx];
        const float d0 = av.x - bv.x + 1e-8f;
        const float d1 = av.y - bv.y + 1e-8f;
        const float d2 = av.z - bv.z + 1e-8f;
        const float d3 = av.w - bv.w + 1e-8f;
        s += d0 * d0 + d1 * d1 + d2 * d2 + d3 * d3;
    }
    #pragma unroll
    for (int o = 16; o; o >>= 1) s += __shfl_xor_sync(0xFFFFFFFFu, s, o);
    __shared__ float ws[4];
    if ((tid & 31) == 0) ws[tid >> 5] = s;
    __syncthreads();
    if (tid == 0) {
        const float t = ws[0] + ws[1] + ws[2] + ws[3];
        g_logd[i] = logf(sqrtf(t) + 1e-8f);
    }
}

// ---------------- kernel 4: deterministic mean reduction ----------------
__global__ void koleo_finish_kernel(float* __restrict__ out) {
    const int tid = threadIdx.x;  // 1024
    float s = 0.f;
    #pragma unroll
    for (int t = 0; t < 8; t++) s += g_logd[tid + t * 1024];
    #pragma unroll
    for (int o = 16; o; o >>= 1) s += __shfl_xor_sync(0xFFFFFFFFu, s, o);
    __shared__ float ws[32];
    if ((tid & 31) == 0) ws[tid >> 5] = s;
    __syncthreads();
    if (tid == 0) {
        float t = 0.f;
        #pragma unroll
        for (int i = 0; i < 32; i++) t += ws[i];
        out[0] = -(t / 8192.f);
    }
}

// ---------------- launch ----------------
extern "C" void kernel_launch(void* const* d_in, const int* in_sizes, int n_in,
                              void* d_out, int out_size) {
    (void)in_sizes; (void)n_in; (void)out_size;
    const float* x = (const float*)d_in[0];
    cudaFuncSetAttribute(koleo_argmax_kernel, cudaFuncAttributeMaxDynamicSharedMemorySize,
                         3 * 49152);
    koleo_normalize_kernel<<<N_ROWS, 256>>>(x);
    koleo_argmax_kernel<<<dim3(64, 2, 1), 256, 3 * 49152>>>();
    koleo_dist_kernel<<<N_ROWS, 128>>>();
    koleo_finish_kernel<<<1, 1024>>>((float*)d_out);
}

// round 4
// speedup vs baseline: 1.1154x; 1.0858x over previous
#include <cuda_runtime.h>
#include <cuda_fp16.h>
#include <cstdint>
#include <math.h>

#define N_ROWS 8192
#define DIMK   1024

// ---------------- scratch (static device memory, no allocs) ----------------
__device__ __align__(16) float  g_Xn[N_ROWS * DIMK];   // 32 MB normalized fp32
__device__ __align__(16) __half g_Xh[N_ROWS * DIMK];   // 16 MB fp16 row-major
__device__ float g_bestv[2 * N_ROWS];
__device__ int   g_besti[2 * N_ROWS];
__device__ float g_logd[N_ROWS];

// ---------------- helpers ----------------
__device__ __forceinline__ uint32_t smem_u32(const void* p) {
    uint32_t a;
    asm("{ .reg .u64 t; cvta.to.shared.u64 t, %1; cvt.u32.u64 %0, t; }" : "=r"(a) : "l"(p));
    return a;
}
__device__ __forceinline__ void cp16(uint32_t dst, const void* src) {
    asm volatile("cp.async.cg.shared.global [%0], [%1], 16;" :: "r"(dst), "l"(src));
}
__device__ __forceinline__ void ldsm4(uint32_t& r0, uint32_t& r1, uint32_t& r2, uint32_t& r3,
                                      uint32_t addr) {
    asm volatile("ldmatrix.sync.aligned.m8n8.x4.shared.b16 {%0,%1,%2,%3}, [%4];"
                 : "=r"(r0), "=r"(r1), "=r"(r2), "=r"(r3) : "r"(addr));
}
// fp16 inputs, fp16 accumulators (2 regs)
__device__ __forceinline__ void mma16816h(uint32_t* c, uint32_t a0, uint32_t a1, uint32_t a2,
                                          uint32_t a3, uint32_t b0, uint32_t b1) {
    asm volatile("mma.sync.aligned.m16n8k16.row.col.f16.f16.f16.f16 "
                 "{%0,%1}, {%2,%3,%4,%5}, {%6,%7}, {%0,%1};"
                 : "+r"(c[0]), "+r"(c[1])
                 : "r"(a0), "r"(a1), "r"(a2), "r"(a3), "r"(b0), "r"(b1));
}

// ---------------- kernel 1: normalize rows, write fp32 + fp16 copies ----------------
__global__ void koleo_normalize_kernel(const float* __restrict__ x) {
    const int row = blockIdx.x;
    const int tid = threadIdx.x;  // 256 threads, 4 elems each
    const float4 v = ((const float4*)(x + (size_t)row * DIMK))[tid];
    float ss = v.x * v.x + v.y * v.y + v.z * v.z + v.w * v.w;
    #pragma unroll
    for (int o = 16; o; o >>= 1) ss += __shfl_xor_sync(0xFFFFFFFFu, ss, o);
    __shared__ float ws[9];
    if ((tid & 31) == 0) ws[tid >> 5] = ss;
    __syncthreads();
    if (tid == 0) {
        float t = 0.f;
        #pragma unroll
        for (int i = 0; i < 8; i++) t += ws[i];
        ws[8] = 1.f / fmaxf(sqrtf(t), 1e-8f);
    }
    __syncthreads();
    const float s = ws[8];
    float4 y; y.x = v.x * s; y.y = v.y * s; y.z = v.z * s; y.w = v.w * s;
    ((float4*)(g_Xn + (size_t)row * DIMK))[tid] = y;

    __half2 h0 = __floats2half2_rn(y.x, y.y);
    __half2 h1 = __floats2half2_rn(y.z, y.w);
    uint2 u;
    u.x = *(const uint32_t*)&h0;
    u.y = *(const uint32_t*)&h1;
    *(uint2*)(g_Xh + (size_t)row * DIMK + tid * 4) = u;
}

// ---------------- kernel 2: fp16 mma.sync GEMM + fused per-row argmax ----------------
// grid (64, 2): 64 row-blocks of 128 rows; each CTA scans 4096 cols as
// 16 N-tiles of 256 columns. 8 warps in 2(m) x 4(n); warp tile 64x64.
// Stage = K-chunk 64: A 128x64 (16KB) + B 256x64 (32KB) = 48KB/buffer, 3 buffers.
// 256 global stages (16 tiles x 16 K-chunks), one __syncthreads per stage.
// Smem swizzle: 16B-chunk index XOR (row & 7).

#define STAGE_BYTES 49152u
#define NSTG 256

__device__ __forceinline__ void copy_stage(uint32_t sbase, int g, int rb, int half, int tid) {
    const int nt = g >> 4;
    const int s = g & 15;
    const uint32_t dst = sbase + (uint32_t)(((uint32_t)g) % 3u) * STAGE_BYTES;
    const __half* gA = g_Xh + (size_t)(rb * 128) * DIMK + s * 64;
    const __half* gB = g_Xh + (size_t)((half * 16 + nt) * 256) * DIMK + s * 64;
    #pragma unroll
    for (int i = 0; i < 4; i++) {
        const int idx = tid + i * 256;
        const int r = idx >> 3, ch = idx & 7;
        const uint32_t doff = (uint32_t)r * 128u + ((uint32_t)(ch ^ (r & 7)) << 4);
        cp16(dst + doff, gA + (size_t)r * DIMK + ch * 8);
    }
    #pragma unroll
    for (int i = 0; i < 8; i++) {
        const int idx = tid + i * 256;
        const int r = idx >> 3, ch = idx & 7;
        const uint32_t doff = (uint32_t)r * 128u + ((uint32_t)(ch ^ (r & 7)) << 4);
        cp16(dst + 16384u + doff, gB + (size_t)r * DIMK + ch * 8);
    }
    asm volatile("cp.async.commit_group;" ::: "memory");
}

__global__ void __launch_bounds__(256) koleo_argmax_kernel() {
    extern __shared__ unsigned char smem[];
    const uint32_t sbase = smem_u32(smem);
    const int tid = threadIdx.x;
    const int lane = tid & 31;
    const int wid = tid >> 5;
    const int wm = wid & 1;        // rows [wm*64, wm*64+64)
    const int wn = wid >> 1;       // cols [wn*64, wn*64+64) within the 256-wide tile
    const int rb = blockIdx.x;
    const int half = blockIdx.y;

    float bestv[8];
    int   besti[8];
    #pragma unroll
    for (int i = 0; i < 8; i++) { bestv[i] = -2.f; besti[i] = 0; }

    uint32_t c2[4][8][2];   // fp16x2 accumulators
    #pragma unroll
    for (int a = 0; a < 4; a++)
        #pragma unroll
        for (int b = 0; b < 8; b++) { c2[a][b][0] = 0u; c2[a][b][1] = 0u; }

    copy_stage(sbase, 0, rb, half, tid);
    copy_stage(sbase, 1, rb, half, tid);

    for (int g = 0; g < NSTG; g++) {
        if (g == NSTG - 1) {
            asm volatile("cp.async.wait_group 0;" ::: "memory");
        } else {
            asm volatile("cp.async.wait_group 1;" ::: "memory");
        }
        __syncthreads();
        if (g + 2 < NSTG) copy_stage(sbase, g + 2, rb, half, tid);

        const uint32_t A = sbase + (uint32_t)(((uint32_t)g) % 3u) * STAGE_BYTES;
        const uint32_t B = A + 16384u;

        #pragma unroll
        for (int t = 0; t < 4; t++) {
            const uint32_t kc = (uint32_t)(t << 1) + (uint32_t)(lane >> 4);
            uint32_t bf[4][4];
            #pragma unroll
            for (int nb = 0; nb < 4; nb++) {
                const uint32_t r = (uint32_t)(wn * 64 + nb * 16 + (lane & 15));
                const uint32_t addr = B + r * 128u + ((kc ^ (r & 7u)) << 4);
                ldsm4(bf[nb][0], bf[nb][1], bf[nb][2], bf[nb][3], addr);
            }
            #pragma unroll
            for (int mt = 0; mt < 4; mt++) {
                const uint32_t r = (uint32_t)(wm * 64 + mt * 16 + (lane & 15));
                const uint32_t addr = A + r * 128u + ((kc ^ (r & 7u)) << 4);
                uint32_t af[4];
                ldsm4(af[0], af[1], af[2], af[3], addr);
                #pragma unroll
                for (int j = 0; j < 8; j++) {
                    mma16816h(c2[mt][j], af[0], af[1], af[2], af[3],
                              bf[j >> 1][j & 1], bf[j >> 1][2 + (j & 1)]);
                }
            }
        }

        if ((g & 15) == 15) {
            // fold this 128x256 tile into the running per-row argmax, reset acc
            const int nt = g >> 4;
            const int colb = (half * 16 + nt) * 256 + wn * 64;
            const int rowb = rb * 128 + wm * 64;
            #pragma unroll
            for (int mt = 0; mt < 4; mt++) {
                #pragma unroll
                for (int rh = 0; rh < 2; rh++) {      // rh=0 -> reg0 (row r), rh=1 -> reg1 (row r+8)
                    const int rloc = mt * 2 + rh;
                    const int grow = rowb + mt * 16 + (lane >> 2) + rh * 8;
                    #pragma unroll
                    for (int j = 0; j < 8; j++) {
                        const __half2 hv = *(const __half2*)&c2[mt][j][rh];
                        const float v0 = __low2float(hv);
                        const float v1 = __high2float(hv);
                        const int col0 = colb + j * 8 + (lane & 3) * 2;
                        if (col0 != grow && v0 > bestv[rloc]) { bestv[rloc] = v0; besti[rloc] = col0; }
                        if (col0 + 1 != grow && v1 > bestv[rloc]) { bestv[rloc] = v1; besti[rloc] = col0 + 1; }
                        c2[mt][j][rh] = 0u;
                    }
                }
            }
        }
    }

    // reduce (max, smallest idx on tie) across the 4 lanes sharing each row
    #pragma unroll
    for (int rl = 0; rl < 8; rl++) {
        float v = bestv[rl]; int i = besti[rl];
        #pragma unroll
        for (int o = 1; o <= 2; o <<= 1) {
            const float ov = __shfl_xor_sync(0xFFFFFFFFu, v, o);
            const int   oi = __shfl_xor_sync(0xFFFFFFFFu, i, o);
            if (ov > v || (ov == v && oi < i)) { v = ov; i = oi; }
        }
        bestv[rl] = v; besti[rl] = i;
    }

    __syncthreads();  // all warps done with stage buffers; reuse smem
    float* svals = (float*)smem;            // [128][4]
    int*   sidx  = (int*)(smem + 2048);     // [128][4]
    if ((lane & 3) == 0) {
        #pragma unroll
        for (int rl = 0; rl < 8; rl++) {
            const int row = wm * 64 + (rl >> 1) * 16 + (lane >> 2) + (rl & 1) * 8;
            svals[row * 4 + wn] = bestv[rl];
            sidx [row * 4 + wn] = besti[rl];
        }
    }
    __syncthreads();
    if (tid < 128) {
        float v = svals[tid * 4]; int i = sidx[tid * 4];
        #pragma unroll
        for (int w = 1; w < 4; w++) {
            const float ov = svals[tid * 4 + w];
            const int   oi = sidx [tid * 4 + w];
            if (ov > v || (ov == v && oi < i)) { v = ov; i = oi; }
        }
        g_bestv[half * N_ROWS + rb * 128 + tid] = v;
        g_besti[half * N_ROWS + rb * 128 + tid] = i;
    }
}

// ---------------- kernel 3: exact fp32 distance to argmax neighbor ----------------
__global__ void koleo_dist_kernel() {
    const int i = blockIdx.x;
    const int tid = threadIdx.x;  // 128
    const float v0 = g_bestv[i], v1 = g_bestv[N_ROWS + i];
    const int j = (v1 > v0) ? g_besti[N_ROWS + i] : g_besti[i];
    const float4* a = (const float4*)(g_Xn + (size_t)i * DIMK);
    const float4* b = (const float4*)(g_Xn + (size_t)j * DIMK);
    float s = 0.f;
    #pragma unroll
    for (int t = 0; t < 2; t++) {
        const int idx = tid + t * 128;
        const float4 av = a[idx], bv = b[idx];
        const float d0 = av.x - bv.x + 1e-8f;
        const float d1 = av.y - bv.y + 1e-8f;
        const float d2 = av.z - bv.z + 1e-8f;
        const float d3 = av.w - bv.w + 1e-8f;
        s += d0 * d0 + d1 * d1 + d2 * d2 + d3 * d3;
    }
    #pragma unroll
    for (int o = 16; o; o >>= 1) s += __shfl_xor_sync(0xFFFFFFFFu, s, o);
    __shared__ float ws[4];
    if ((tid & 31) == 0) ws[tid >> 5] = s;
    __syncthreads();
    if (tid == 0) {
        const float t = ws[0] + ws[1] + ws[2] + ws[3];
        g_logd[i] = logf(sqrtf(t) + 1e-8f);
    }
}

// ---------------- kernel 4: deterministic mean reduction ----------------
__global__ void koleo_finish_kernel(float* __restrict__ out) {
    const int tid = threadIdx.x;  // 1024
    float s = 0.f;
    #pragma unroll
    for (int t = 0; t < 8; t++) s += g_logd[tid + t * 1024];
    #pragma unroll
    for (int o = 16; o; o >>= 1) s += __shfl_xor_sync(0xFFFFFFFFu, s, o);
    __shared__ float ws[32];
    if ((tid & 31) == 0) ws[tid >> 5] = s;
    __syncthreads();
    if (tid == 0) {
        float t = 0.f;
        #pragma unroll
        for (int i = 0; i < 32; i++) t += ws[i];
        out[0] = -(t / 8192.f);
    }
}

// ---------------- launch ----------------
extern "C" void kernel_launch(void* const* d_in, const int* in_sizes, int n_in,
                              void* d_out, int out_size) {
    (void)in_sizes; (void)n_in; (void)out_size;
    const float* x = (const float*)d_in[0];
    cudaFuncSetAttribute(koleo_argmax_kernel, cudaFuncAttributeMaxDynamicSharedMemorySize,
                         3 * 49152);
    koleo_normalize_kernel<<<N_ROWS, 256>>>(x);
    koleo_argmax_kernel<<<dim3(64, 2, 1), 256, 3 * 49152>>>();
    koleo_dist_kernel<<<N_ROWS, 128>>>();
    koleo_finish_kernel<<<1, 1024>>>((float*)d_out);
}

// round 5
// speedup vs baseline: 1.2891x; 1.1558x over previous
#include <cuda_runtime.h>
#include <cuda_fp16.h>
#include <cstdint>
#include <math.h>

#define N_ROWS 8192
#define DIMK   1024
#define NCTA   148
#define NJOBS  2048          // 64 row-blocks x 32 col-tiles (256 wide)
#define STAGE_BYTES 49152u

// ---------------- scratch (static device memory, no allocs) ----------------
__device__ __align__(16) float  g_Xn[N_ROWS * DIMK];   // 32 MB normalized fp32
__device__ __align__(16) __half g_Xh[N_ROWS * DIMK];   // 16 MB fp16 row-major
__device__ unsigned long long g_best[N_ROWS];          // packed (enc(val)<<32 | ~col)
__device__ float g_logd[N_ROWS];

// ---------------- helpers ----------------
__device__ __forceinline__ uint32_t smem_u32(const void* p) {
    uint32_t a;
    asm("{ .reg .u64 t; cvta.to.shared.u64 t, %1; cvt.u32.u64 %0, t; }" : "=r"(a) : "l"(p));
    return a;
}
__device__ __forceinline__ void cp16(uint32_t dst, const void* src) {
    asm volatile("cp.async.cg.shared.global [%0], [%1], 16;" :: "r"(dst), "l"(src));
}
__device__ __forceinline__ void ldsm4(uint32_t& r0, uint32_t& r1, uint32_t& r2, uint32_t& r3,
                                      uint32_t addr) {
    asm volatile("ldmatrix.sync.aligned.m8n8.x4.shared.b16 {%0,%1,%2,%3}, [%4];"
                 : "=r"(r0), "=r"(r1), "=r"(r2), "=r"(r3) : "r"(addr));
}
__device__ __forceinline__ void mma16816h(uint32_t* c, uint32_t a0, uint32_t a1, uint32_t a2,
                                          uint32_t a3, uint32_t b0, uint32_t b1) {
    asm volatile("mma.sync.aligned.m16n8k16.row.col.f16.f16.f16.f16 "
                 "{%0,%1}, {%2,%3,%4,%5}, {%6,%7}, {%0,%1};"
                 : "+r"(c[0]), "+r"(c[1])
                 : "r"(a0), "r"(a1), "r"(a2), "r"(a3), "r"(b0), "r"(b1));
}
// monotonic float->u32 (total order preserved, incl. negatives)
__device__ __forceinline__ uint32_t fenc(float v) {
    const uint32_t u = __float_as_uint(v);
    return (u & 0x80000000u) ? ~u : (u | 0x80000000u);
}

// ---------------- kernel 1: normalize rows, write fp32 + fp16; reset g_best ----------------
__global__ void koleo_normalize_kernel(const float* __restrict__ x) {
    const int row = blockIdx.x;
    const int tid = threadIdx.x;  // 256 threads, 4 elems each
    if (tid == 0) g_best[row] = 0ull;
    const float4 v = ((const float4*)(x + (size_t)row * DIMK))[tid];
    float ss = v.x * v.x + v.y * v.y + v.z * v.z + v.w * v.w;
    #pragma unroll
    for (int o = 16; o; o >>= 1) ss += __shfl_xor_sync(0xFFFFFFFFu, ss, o);
    __shared__ float ws[9];
    if ((tid & 31) == 0) ws[tid >> 5] = ss;
    __syncthreads();
    if (tid == 0) {
        float t = 0.f;
        #pragma unroll
        for (int i = 0; i < 8; i++) t += ws[i];
        ws[8] = 1.f / fmaxf(sqrtf(t), 1e-8f);
    }
    __syncthreads();
    const float s = ws[8];
    float4 y; y.x = v.x * s; y.y = v.y * s; y.z = v.z * s; y.w = v.w * s;
    ((float4*)(g_Xn + (size_t)row * DIMK))[tid] = y;

    __half2 h0 = __floats2half2_rn(y.x, y.y);
    __half2 h1 = __floats2half2_rn(y.z, y.w);
    uint2 u;
    u.x = *(const uint32_t*)&h0;
    u.y = *(const uint32_t*)&h1;
    *(uint2*)(g_Xh + (size_t)row * DIMK + tid * 4) = u;
}

// ---------------- kernel 2: persistent fp16 GEMM + fused argmax ----------------
// 148 CTAs; job j in [0,2048): rb = j>>5 (128 rows), nt = j&31 (256 cols).
// CTA c runs jobs c, c+148, ... Stage = K-chunk 64 (16 stages per job), streamed
// continuously across jobs: 4 smem buffers (48KB each), prefetch depth 3,
// one __syncthreads per stage. Swizzle: 16B-chunk idx XOR (row & 7).
// Per-row argmax merged chip-wide via atomicMax on u64 keys.

__device__ __forceinline__ void copy_stream(uint32_t sbase, int cta, int s, int S, int tid) {
    if (s < S) {
        const int job = cta + (s >> 4) * NCTA;
        const int nt = job & 31, rb = job >> 5, kc = s & 15;
        const uint32_t dst = sbase + (uint32_t)(s & 3) * STAGE_BYTES;
        const __half* gA = g_Xh + (size_t)(rb * 128) * DIMK + kc * 64;
        const __half* gB = g_Xh + (size_t)(nt * 256) * DIMK + kc * 64;
        #pragma unroll
        for (int i = 0; i < 4; i++) {
            const int idx = tid + i * 256;
            const int r = idx >> 3, ch = idx & 7;
            const uint32_t doff = (uint32_t)r * 128u + ((uint32_t)(ch ^ (r & 7)) << 4);
            cp16(dst + doff, gA + (size_t)r * DIMK + ch * 8);
        }
        #pragma unroll
        for (int i = 0; i < 8; i++) {
            const int idx = tid + i * 256;
            const int r = idx >> 3, ch = idx & 7;
            const uint32_t doff = (uint32_t)r * 128u + ((uint32_t)(ch ^ (r & 7)) << 4);
            cp16(dst + 16384u + doff, gB + (size_t)r * DIMK + ch * 8);
        }
    }
    asm volatile("cp.async.commit_group;" ::: "memory");
}

__global__ void __launch_bounds__(256) koleo_argmax_kernel() {
    extern __shared__ unsigned char smem[];
    const uint32_t sbase = smem_u32(smem);
    const int tid = threadIdx.x;
    const int lane = tid & 31;
    const int wid = tid >> 5;
    const int wm = wid & 1;        // rows [wm*64, wm*64+64)
    const int wn = wid >> 1;       // cols [wn*64, wn*64+64) within 256-wide tile
    const int cta = blockIdx.x;
    const int m = (NJOBS - cta + NCTA - 1) / NCTA;   // jobs for this CTA
    const int S = m * 16;

    float bestv[8];
    int   besti[8];
    #pragma unroll
    for (int i = 0; i < 8; i++) { bestv[i] = -2.f; besti[i] = 0; }

    uint32_t c2[4][8][2];   // fp16x2 accumulators
    #pragma unroll
    for (int a = 0; a < 4; a++)
        #pragma unroll
        for (int b = 0; b < 8; b++) { c2[a][b][0] = 0u; c2[a][b][1] = 0u; }

    copy_stream(sbase, cta, 0, S, tid);
    copy_stream(sbase, cta, 1, S, tid);
    copy_stream(sbase, cta, 2, S, tid);

    for (int s = 0; s < S; s++) {
        asm volatile("cp.async.wait_group 2;" ::: "memory");
        __syncthreads();
        copy_stream(sbase, cta, s + 3, S, tid);

        const uint32_t A = sbase + (uint32_t)(s & 3) * STAGE_BYTES;
        const uint32_t B = A + 16384u;

        #pragma unroll
        for (int t = 0; t < 4; t++) {
            const uint32_t kc = (uint32_t)(t << 1) + (uint32_t)(lane >> 4);
            uint32_t bf[4][4], af[4][4];
            #pragma unroll
            for (int nb = 0; nb < 4; nb++) {
                const uint32_t r = (uint32_t)(wn * 64 + nb * 16 + (lane & 15));
                const uint32_t addr = B + r * 128u + ((kc ^ (r & 7u)) << 4);
                ldsm4(bf[nb][0], bf[nb][1], bf[nb][2], bf[nb][3], addr);
            }
            #pragma unroll
            for (int mt = 0; mt < 4; mt++) {
                const uint32_t r = (uint32_t)(wm * 64 + mt * 16 + (lane & 15));
                const uint32_t addr = A + r * 128u + ((kc ^ (r & 7u)) << 4);
                ldsm4(af[mt][0], af[mt][1], af[mt][2], af[mt][3], addr);
            }
            #pragma unroll
            for (int mt = 0; mt < 4; mt++)
                #pragma unroll
                for (int j = 0; j < 8; j++)
                    mma16816h(c2[mt][j], af[mt][0], af[mt][1], af[mt][2], af[mt][3],
                              bf[j >> 1][j & 1], bf[j >> 1][2 + (j & 1)]);
        }

        if ((s & 15) == 15) {
            // end of job: fold 128x256 tile into per-row best, merge, reset
            const int job = cta + (s >> 4) * NCTA;
            const int colb = (job & 31) * 256 + wn * 64;
            const int rowb = (job >> 5) * 128 + wm * 64;
            #pragma unroll
            for (int mt = 0; mt < 4; mt++) {
                #pragma unroll
                for (int rh = 0; rh < 2; rh++) {
                    const int rloc = mt * 2 + rh;
                    const int grow = rowb + mt * 16 + (lane >> 2) + rh * 8;
                    #pragma unroll
                    for (int j = 0; j < 8; j++) {
                        const __half2 hv = *(const __half2*)&c2[mt][j][rh];
                        const float v0 = __low2float(hv);
                        const float v1 = __high2float(hv);
                        const int col0 = colb + j * 8 + (lane & 3) * 2;
                        if (col0 != grow && v0 > bestv[rloc]) { bestv[rloc] = v0; besti[rloc] = col0; }
                        if (col0 + 1 != grow && v1 > bestv[rloc]) { bestv[rloc] = v1; besti[rloc] = col0 + 1; }
                        c2[mt][j][rh] = 0u;
                    }
                }
            }
            #pragma unroll
            for (int rloc = 0; rloc < 8; rloc++) {
                unsigned long long key =
                    ((unsigned long long)fenc(bestv[rloc]) << 32) |
                    (unsigned long long)(0xFFFFFFFFu - (uint32_t)besti[rloc]);
                #pragma unroll
                for (int o = 1; o <= 2; o <<= 1) {
                    const unsigned long long ok = __shfl_xor_sync(0xFFFFFFFFu, key, o);
                    if (ok > key) key = ok;
                }
                if ((lane & 3) == 0) {
                    const int grow = rowb + (rloc >> 1) * 16 + (lane >> 2) + (rloc & 1) * 8;
                    atomicMax(&g_best[grow], key);   // RED.MAX.U64, order-independent
                }
                bestv[rloc] = -2.f; besti[rloc] = 0;
            }
        }
    }
}

// ---------------- kernel 3: exact fp32 distance to argmax neighbor ----------------
__global__ void koleo_dist_kernel() {
    const int i = blockIdx.x;
    const int tid = threadIdx.x;  // 128
    const int j = (int)(0xFFFFFFFFu - (uint32_t)g_best[i]);
    const float4* a = (const float4*)(g_Xn + (size_t)i * DIMK);
    const float4* b = (const float4*)(g_Xn + (size_t)j * DIMK);
    float s = 0.f;
    #pragma unroll
    for (int t = 0; t < 2; t++) {
        const int idx = tid + t * 128;
        const float4 av = a[idx], bv = b[idx];
        const float d0 = av.x - bv.x + 1e-8f;
        const float d1 = av.y - bv.y + 1e-8f;
        const float d2 = av.z - bv.z + 1e-8f;
        const float d3 = av.w - bv.w + 1e-8f;
        s += d0 * d0 + d1 * d1 + d2 * d2 + d3 * d3;
    }
    #pragma unroll
    for (int o = 16; o; o >>= 1) s += __shfl_xor_sync(0xFFFFFFFFu, s, o);
    __shared__ float ws[4];
    if ((tid & 31) == 0) ws[tid >> 5] = s;
    __syncthreads();
    if (tid == 0) {
        const float t = ws[0] + ws[1] + ws[2] + ws[3];
        g_logd[i] = logf(sqrtf(t) + 1e-8f);
    }
}

// ---------------- kernel 4: deterministic mean reduction ----------------
__global__ void koleo_finish_kernel(float* __restrict__ out) {
    const int tid = threadIdx.x;  // 1024
    float s = 0.f;
    #pragma unroll
    for (int t = 0; t < 8; t++) s += g_logd[tid + t * 1024];
    #pragma unroll
    for (int o = 16; o; o >>= 1) s += __shfl_xor_sync(0xFFFFFFFFu, s, o);
    __shared__ float ws[32];
    if ((tid & 31) == 0) ws[tid >> 5] = s;
    __syncthreads();
    if (tid == 0) {
        float t = 0.f;
        #pragma unroll
        for (int i = 0; i < 32; i++) t += ws[i];
        out[0] = -(t / 8192.f);
    }
}

// ---------------- launch ----------------
extern "C" void kernel_launch(void* const* d_in, const int* in_sizes, int n_in,
                              void* d_out, int out_size) {
    (void)in_sizes; (void)n_in; (void)out_size;
    const float* x = (const float*)d_in[0];
    cudaFuncSetAttribute(koleo_argmax_kernel, cudaFuncAttributeMaxDynamicSharedMemorySize,
                         4 * 49152);
    koleo_normalize_kernel<<<N_ROWS, 256>>>(x);
    koleo_argmax_kernel<<<NCTA, 256, 4 * 49152>>>();
    koleo_dist_kernel<<<N_ROWS, 128>>>();
    koleo_finish_kernel<<<1, 1024>>>((float*)d_out);
}

// round 6
// speedup vs baseline: 1.8346x; 1.4231x over previous
#include <cuda_runtime.h>
#include <cuda_fp16.h>
#include <cstdint>
#include <math.h>

#define N_ROWS 8192
#define DIMK   1024
#define NCTA   148
#define NJOBS_T 1056         // upper-triangle 128x256 tiles: sum_{rb} (32 - rb/2)
#define STAGE_BYTES 49152u

// ---------------- scratch (static device memory, no allocs) ----------------
__device__ __align__(16) float  g_Xn[N_ROWS * DIMK];   // 32 MB normalized fp32
__device__ __align__(16) __half g_Xh[N_ROWS * DIMK];   // 16 MB fp16 row-major
__device__ unsigned long long g_best[N_ROWS];          // packed (enc(val)<<32 | ~col)
__device__ float g_logd[N_ROWS];

// ---------------- helpers ----------------
__device__ __forceinline__ uint32_t smem_u32(const void* p) {
    uint32_t a;
    asm("{ .reg .u64 t; cvta.to.shared.u64 t, %1; cvt.u32.u64 %0, t; }" : "=r"(a) : "l"(p));
    return a;
}
__device__ __forceinline__ void cp16(uint32_t dst, const void* src) {
    asm volatile("cp.async.cg.shared.global [%0], [%1], 16;" :: "r"(dst), "l"(src));
}
__device__ __forceinline__ void ldsm4(uint32_t& r0, uint32_t& r1, uint32_t& r2, uint32_t& r3,
                                      uint32_t addr) {
    asm volatile("ldmatrix.sync.aligned.m8n8.x4.shared.b16 {%0,%1,%2,%3}, [%4];"
                 : "=r"(r0), "=r"(r1), "=r"(r2), "=r"(r3) : "r"(addr));
}
__device__ __forceinline__ void mma16816h(uint32_t* c, uint32_t a0, uint32_t a1, uint32_t a2,
                                          uint32_t a3, uint32_t b0, uint32_t b1) {
    asm volatile("mma.sync.aligned.m16n8k16.row.col.f16.f16.f16.f16 "
                 "{%0,%1}, {%2,%3,%4,%5}, {%6,%7}, {%0,%1};"
                 : "+r"(c[0]), "+r"(c[1])
                 : "r"(a0), "r"(a1), "r"(a2), "r"(a3), "r"(b0), "r"(b1));
}
// monotonic float->u32 (total order preserved, incl. negatives)
__device__ __forceinline__ uint32_t fenc(float v) {
    const uint32_t u = __float_as_uint(v);
    return (u & 0x80000000u) ? ~u : (u | 0x80000000u);
}
// job index -> (rb, nt) for the upper-triangle tile list.
// Pair u (rb = 2u, 2u+1) has 2*(32-u) jobs; cumulative S(u) = u*(65-u).
__device__ __forceinline__ uint32_t job_decode(int jj) {
    int u = 0;
    #pragma unroll 1
    while ((u + 1) * (65 - (u + 1)) <= jj) u++;
    const int r = jj - u * (65 - u);
    const int cnt = 32 - u;
    const int rb = 2 * u + (r >= cnt);
    const int nt = u + (r >= cnt ? r - cnt : r);
    return ((uint32_t)rb << 8) | (uint32_t)nt;
}

// ---------------- kernel 1: normalize rows, write fp32 + fp16; reset g_best ----------------
__global__ void koleo_normalize_kernel(const float* __restrict__ x) {
    const int row = blockIdx.x;
    const int tid = threadIdx.x;  // 256 threads, 4 elems each
    if (tid == 0) g_best[row] = 0ull;
    const float4 v = ((const float4*)(x + (size_t)row * DIMK))[tid];
    float ss = v.x * v.x + v.y * v.y + v.z * v.z + v.w * v.w;
    #pragma unroll
    for (int o = 16; o; o >>= 1) ss += __shfl_xor_sync(0xFFFFFFFFu, ss, o);
    __shared__ float ws[9];
    if ((tid & 31) == 0) ws[tid >> 5] = ss;
    __syncthreads();
    if (tid == 0) {
        float t = 0.f;
        #pragma unroll
        for (int i = 0; i < 8; i++) t += ws[i];
        ws[8] = 1.f / fmaxf(sqrtf(t), 1e-8f);
    }
    __syncthreads();
    const float s = ws[8];
    float4 y; y.x = v.x * s; y.y = v.y * s; y.z = v.z * s; y.w = v.w * s;
    ((float4*)(g_Xn + (size_t)row * DIMK))[tid] = y;

    __half2 h0 = __floats2half2_rn(y.x, y.y);
    __half2 h1 = __floats2half2_rn(y.z, y.w);
    uint2 u;
    u.x = *(const uint32_t*)&h0;
    u.y = *(const uint32_t*)&h1;
    *(uint2*)(g_Xh + (size_t)row * DIMK + tid * 4) = u;
}

// ---------------- kernel 2: persistent fp16 GEMM over the upper triangle ----------------
// 148 CTAs; CTA c runs triangle-jobs c, c+148, ... (max 8). Tile = 128 rows x 256 cols.
// Stage = K-chunk 64 (16/job), streamed continuously: 4 smem buffers, depth 3,
// one __syncthreads per stage. Each finished tile folds BOTH row-side and
// column-side (symmetry) candidates into g_best via order-independent atomicMax.

__device__ __forceinline__ void copy_stream(uint32_t sbase, const uint32_t* jtab,
                                            int s, int S, int tid) {
    if (s < S) {
        const uint32_t rbnt = jtab[s >> 4];
        const int rb = (int)(rbnt >> 8), nt = (int)(rbnt & 255u), kc = s & 15;
        const uint32_t dst = sbase + (uint32_t)(s & 3) * STAGE_BYTES;
        const __half* gA = g_Xh + (size_t)(rb * 128) * DIMK + kc * 64;
        const __half* gB = g_Xh + (size_t)(nt * 256) * DIMK + kc * 64;
        #pragma unroll
        for (int i = 0; i < 4; i++) {
            const int idx = tid + i * 256;
            const int r = idx >> 3, ch = idx & 7;
            const uint32_t doff = (uint32_t)r * 128u + ((uint32_t)(ch ^ (r & 7)) << 4);
            cp16(dst + doff, gA + (size_t)r * DIMK + ch * 8);
        }
        #pragma unroll
        for (int i = 0; i < 8; i++) {
            const int idx = tid + i * 256;
            const int r = idx >> 3, ch = idx & 7;
            const uint32_t doff = (uint32_t)r * 128u + ((uint32_t)(ch ^ (r & 7)) << 4);
            cp16(dst + 16384u + doff, gB + (size_t)r * DIMK + ch * 8);
        }
    }
    asm volatile("cp.async.commit_group;" ::: "memory");
}

__global__ void __launch_bounds__(256) koleo_argmax_kernel() {
    extern __shared__ unsigned char smem[];
    const uint32_t sbase = smem_u32(smem);
    uint32_t* jtab = (uint32_t*)(smem + 4 * STAGE_BYTES);   // per-CTA job table (<=8)
    const int tid = threadIdx.x;
    const int lane = tid & 31;
    const int wid = tid >> 5;
    const int wm = wid & 1;        // rows [wm*64, wm*64+64)
    const int wn = wid >> 1;       // cols [wn*64, wn*64+64) within 256-wide tile
    const int cta = blockIdx.x;
    const int m = (NJOBS_T - cta + NCTA - 1) / NCTA;   // jobs for this CTA
    const int S = m * 16;

    if (tid < 8 && tid < m) jtab[tid] = job_decode(cta + tid * NCTA);
    __syncthreads();

    uint32_t c2[4][8][2];   // fp16x2 accumulators
    #pragma unroll
    for (int a = 0; a < 4; a++)
        #pragma unroll
        for (int b = 0; b < 8; b++) { c2[a][b][0] = 0u; c2[a][b][1] = 0u; }

    copy_stream(sbase, jtab, 0, S, tid);
    copy_stream(sbase, jtab, 1, S, tid);
    copy_stream(sbase, jtab, 2, S, tid);

    for (int s = 0; s < S; s++) {
        asm volatile("cp.async.wait_group 2;" ::: "memory");
        __syncthreads();
        copy_stream(sbase, jtab, s + 3, S, tid);

        const uint32_t A = sbase + (uint32_t)(s & 3) * STAGE_BYTES;
        const uint32_t B = A + 16384u;

        #pragma unroll
        for (int t = 0; t < 4; t++) {
            const uint32_t kc = (uint32_t)(t << 1) + (uint32_t)(lane >> 4);
            uint32_t bf[4][4], af[4][4];
            #pragma unroll
            for (int nb = 0; nb < 4; nb++) {
                const uint32_t r = (uint32_t)(wn * 64 + nb * 16 + (lane & 15));
                const uint32_t addr = B + r * 128u + ((kc ^ (r & 7u)) << 4);
                ldsm4(bf[nb][0], bf[nb][1], bf[nb][2], bf[nb][3], addr);
            }
            #pragma unroll
            for (int mt = 0; mt < 4; mt++) {
                const uint32_t r = (uint32_t)(wm * 64 + mt * 16 + (lane & 15));
                const uint32_t addr = A + r * 128u + ((kc ^ (r & 7u)) << 4);
                ldsm4(af[mt][0], af[mt][1], af[mt][2], af[mt][3], addr);
            }
            #pragma unroll
            for (int mt = 0; mt < 4; mt++)
                #pragma unroll
                for (int j = 0; j < 8; j++)
                    mma16816h(c2[mt][j], af[mt][0], af[mt][1], af[mt][2], af[mt][3],
                              bf[j >> 1][j & 1], bf[j >> 1][2 + (j & 1)]);
        }

        if ((s & 15) == 15) {
            const uint32_t rbnt = jtab[s >> 4];
            const int rb = (int)(rbnt >> 8), nt = (int)(rbnt & 255u);
            const int colb = nt * 256 + wn * 64;   // warp's global col base
            const int rowb = rb * 128 + wm * 64;   // warp's global row base

            // ---- column-side fold (symmetry): per-column max over 128 rows ----
            #pragma unroll
            for (int j = 0; j < 8; j++) {
                #pragma unroll
                for (int h = 0; h < 2; h++) {
                    const int gcol = colb + j * 8 + (lane & 3) * 2 + h;
                    float cv = -2.f; int cr = 0;
                    #pragma unroll
                    for (int mt = 0; mt < 4; mt++) {
                        #pragma unroll
                        for (int rh = 0; rh < 2; rh++) {
                            const __half2 hv = *(const __half2*)&c2[mt][j][rh];
                            const float v = h ? __high2float(hv) : __low2float(hv);
                            const int grow = rowb + mt * 16 + (lane >> 2) + rh * 8;
                            if (grow != gcol && (v > cv || (v == cv && grow < cr))) {
                                cv = v; cr = grow;
                            }
                        }
                    }
                    unsigned long long key =
                        ((unsigned long long)fenc(cv) << 32) |
                        (unsigned long long)(0xFFFFFFFFu - (uint32_t)cr);
                    #pragma unroll
                    for (int o = 4; o <= 16; o <<= 1) {
                        const unsigned long long ok = __shfl_xor_sync(0xFFFFFFFFu, key, o);
                        if (ok > key) key = ok;
                    }
                    if (lane < 4) atomicMax(&g_best[gcol], key);
                }
            }

            // ---- row-side fold + accumulator reset ----
            float bestv[8];
            int   besti[8];
            #pragma unroll
            for (int i = 0; i < 8; i++) { bestv[i] = -2.f; besti[i] = 0; }
            #pragma unroll
            for (int mt = 0; mt < 4; mt++) {
                #pragma unroll
                for (int rh = 0; rh < 2; rh++) {
                    const int rloc = mt * 2 + rh;
                    const int grow = rowb + mt * 16 + (lane >> 2) + rh * 8;
                    #pragma unroll
                    for (int j = 0; j < 8; j++) {
                        const __half2 hv = *(const __half2*)&c2[mt][j][rh];
                        const float v0 = __low2float(hv);
                        const float v1 = __high2float(hv);
                        const int col0 = colb + j * 8 + (lane & 3) * 2;
                        if (col0 != grow && v0 > bestv[rloc]) { bestv[rloc] = v0; besti[rloc] = col0; }
                        if (col0 + 1 != grow && v1 > bestv[rloc]) { bestv[rloc] = v1; besti[rloc] = col0 + 1; }
                        c2[mt][j][rh] = 0u;
                    }
                }
            }
            #pragma unroll
            for (int rloc = 0; rloc < 8; rloc++) {
                unsigned long long key =
                    ((unsigned long long)fenc(bestv[rloc]) << 32) |
                    (unsigned long long)(0xFFFFFFFFu - (uint32_t)besti[rloc]);
                #pragma unroll
                for (int o = 1; o <= 2; o <<= 1) {
                    const unsigned long long ok = __shfl_xor_sync(0xFFFFFFFFu, key, o);
                    if (ok > key) key = ok;
                }
                if ((lane & 3) == 0) {
                    const int grow = rowb + (rloc >> 1) * 16 + (lane >> 2) + (rloc & 1) * 8;
                    atomicMax(&g_best[grow], key);
                }
            }
        }
    }
}

// ---------------- kernel 3: exact fp32 distance to argmax neighbor ----------------
__global__ void koleo_dist_kernel() {
    const int i = blockIdx.x;
    const int tid = threadIdx.x;  // 128
    const int j = (int)(0xFFFFFFFFu - (uint32_t)g_best[i]);
    const float4* a = (const float4*)(g_Xn + (size_t)i * DIMK);
    const float4* b = (const float4*)(g_Xn + (size_t)j * DIMK);
    float s = 0.f;
    #pragma unroll
    for (int t = 0; t < 2; t++) {
        const int idx = tid + t * 128;
        const float4 av = a[idx], bv = b[idx];
        const float d0 = av.x - bv.x + 1e-8f;
        const float d1 = av.y - bv.y + 1e-8f;
        const float d2 = av.z - bv.z + 1e-8f;
        const float d3 = av.w - bv.w + 1e-8f;
        s += d0 * d0 + d1 * d1 + d2 * d2 + d3 * d3;
    }
    #pragma unroll
    for (int o = 16; o; o >>= 1) s += __shfl_xor_sync(0xFFFFFFFFu, s, o);
    __shared__ float ws[4];
    if ((tid & 31) == 0) ws[tid >> 5] = s;
    __syncthreads();
    if (tid == 0) {
        const float t = ws[0] + ws[1] + ws[2] + ws[3];
        g_logd[i] = logf(sqrtf(t) + 1e-8f);
    }
}

// ---------------- kernel 4: deterministic mean reduction ----------------
__global__ void koleo_finish_kernel(float* __restrict__ out) {
    const int tid = threadIdx.x;  // 1024
    float s = 0.f;
    #pragma unroll
    for (int t = 0; t < 8; t++) s += g_logd[tid + t * 1024];
    #pragma unroll
    for (int o = 16; o; o >>= 1) s += __shfl_xor_sync(0xFFFFFFFFu, s, o);
    __shared__ float ws[32];
    if ((tid & 31) == 0) ws[tid >> 5] = s;
    __syncthreads();
    if (tid == 0) {
        float t = 0.f;
        #pragma unroll
        for (int i = 0; i < 32; i++) t += ws[i];
        out[0] = -(t / 8192.f);
    }
}

// ---------------- launch ----------------
extern "C" void kernel_launch(void* const* d_in, const int* in_sizes, int n_in,
                              void* d_out, int out_size) {
    (void)in_sizes; (void)n_in; (void)out_size;
    const float* x = (const float*)d_in[0];
    const int smem_bytes = 4 * 49152 + 64;
    cudaFuncSetAttribute(koleo_argmax_kernel, cudaFuncAttributeMaxDynamicSharedMemorySize,
                         smem_bytes);
    koleo_normalize_kernel<<<N_ROWS, 256>>>(x);
    koleo_argmax_kernel<<<NCTA, 256, smem_bytes>>>();
    koleo_dist_kernel<<<N_ROWS, 128>>>();
    koleo_finish_kernel<<<1, 1024>>>((float*)d_out);
}